// round 9
// baseline (speedup 1.0000x reference)
#include <cuda_runtime.h>
#include <stdint.h>
#include <math.h>

#define Bx 8
#define Cx 4
#define Hx 384
#define Wx 384
#define SLICE (Hx*Wx)          // 147456
#define NSLICE (Bx*Cx)         // 32
#define BIGI 768               // = H + W, finite sentinel (matches reference)
#define INFP 0x3FFF3FFFu       // packed u16x2 "infinity" (saturating math keeps it big)
#define ONEP 0x00010001u
#define PADSQ 0xFE01FE01u      // packed 255^2: pad candidates always lose (>16)

// Scratch (no cudaMalloc allowed).
__device__ unsigned long long g_pack[Bx*SLICE]; // [b][h][w] -> g for 4 classes, u16x4 (9 MB)
__device__ unsigned int   g_dmax_bits[NSLICE];
__device__ double         g_S[NSLICE];          // sum of p_c over target pixels
__device__ double         g_acc;                // sum of p_c * dt over non-target pixels
__device__ unsigned int   g_count;              // zero-init; reset by last k_row block

__device__ __forceinline__ float sqrt_approx(float x) {
    float r;
    asm("sqrt.approx.f32 %0, %1;" : "=f"(r) : "f"(x));
    return r;
}

// ---------------------------------------------------------------------------
// Phase 1: vertical 1D distance per (b,w) column for ALL 4 classes packed
// u16x4. One warp per column; lane owns a 12-pixel h-segment. Exact segmented
// min-plus scan; unclamped math + final clamp(768) == reference's per-step
// clamp since increments are +1.
__global__ void __launch_bounds__(256) k_phase1(const int* __restrict__ targets) {
    __shared__ unsigned long long sg[Hx][9];   // 27 KB staging (pad vs bank conflicts)

    int tid = threadIdx.x, wid = tid >> 5, lane = tid & 31;
    if (blockIdx.x == 0 && tid < NSLICE) {     // fused init
        g_dmax_bits[tid] = 0u; g_S[tid] = 0.0;
        if (tid == 0) g_acc = 0.0;
    }

    int b  = blockIdx.x / (Wx / 8);
    int w0 = (blockIdx.x % (Wx / 8)) * 8;
    int w  = w0 + wid;
    const int* tb = targets + (size_t)b * SLICE + w;
    int h0 = lane * 12;

    uint32_t mlo[12], mhi[12];
    #pragma unroll
    for (int i = 0; i < 12; ++i) {
        int t = __ldg(&tb[(h0 + i) * Wx]);
        mlo[i] = (t == 0) ? 0xFFFF0000u : (t == 1) ? 0x0000FFFFu : 0xFFFFFFFFu;
        mhi[i] = (t == 2) ? 0xFFFF0000u : (t == 3) ? 0x0000FFFFu : 0xFFFFFFFFu;
    }

    // Local scans -> segment summaries
    uint32_t flo = INFP, fhi = INFP;
    #pragma unroll
    for (int i = 0; i < 12; ++i) { flo = __vaddus2(flo, ONEP) & mlo[i]; fhi = __vaddus2(fhi, ONEP) & mhi[i]; }
    uint32_t blo = INFP, bhi = INFP;
    #pragma unroll
    for (int i = 11; i >= 0; --i) { blo = __vaddus2(blo, ONEP) & mlo[i]; bhi = __vaddus2(bhi, ONEP) & mhi[i]; }

    // Warp min-plus inclusive scans (forward: up; backward: down)
    uint32_t filo = flo, fihi = fhi, bilo = blo, bihi = bhi;
    #pragma unroll
    for (int d = 1; d < 32; d <<= 1) {
        uint32_t k = ((12u * d) << 16) | (12u * d);
        uint32_t a0 = __shfl_up_sync(0xffffffffu, filo, d);
        uint32_t a1 = __shfl_up_sync(0xffffffffu, fihi, d);
        if (lane >= d) { filo = __vminu2(filo, __vaddus2(a0, k)); fihi = __vminu2(fihi, __vaddus2(a1, k)); }
        uint32_t c0 = __shfl_down_sync(0xffffffffu, bilo, d);
        uint32_t c1 = __shfl_down_sync(0xffffffffu, bihi, d);
        if (lane < 32 - d) { bilo = __vminu2(bilo, __vaddus2(c0, k)); bihi = __vminu2(bihi, __vaddus2(c1, k)); }
    }
    uint32_t cflo = __shfl_up_sync(0xffffffffu, filo, 1);
    uint32_t cfhi = __shfl_up_sync(0xffffffffu, fihi, 1);
    if (lane == 0) { cflo = INFP; cfhi = INFP; }
    uint32_t cblo = __shfl_down_sync(0xffffffffu, bilo, 1);
    uint32_t cbhi = __shfl_down_sync(0xffffffffu, bihi, 1);
    if (lane == 31) { cblo = INFP; cbhi = INFP; }

    unsigned long long Df[12];
    uint32_t rlo = cflo, rhi = cfhi;
    flo = INFP; fhi = INFP;
    #pragma unroll
    for (int i = 0; i < 12; ++i) {
        rlo = __vaddus2(rlo, ONEP); rhi = __vaddus2(rhi, ONEP);
        flo = __vaddus2(flo, ONEP) & mlo[i]; fhi = __vaddus2(fhi, ONEP) & mhi[i];
        uint32_t xlo = __vminu2(flo, rlo), xhi = __vminu2(fhi, rhi);
        Df[i] = ((unsigned long long)xhi << 32) | xlo;
    }
    const uint32_t CLP = ((uint32_t)BIGI << 16) | (uint32_t)BIGI;
    rlo = cblo; rhi = cbhi; blo = INFP; bhi = INFP;
    #pragma unroll
    for (int i = 11; i >= 0; --i) {
        rlo = __vaddus2(rlo, ONEP); rhi = __vaddus2(rhi, ONEP);
        blo = __vaddus2(blo, ONEP) & mlo[i]; bhi = __vaddus2(bhi, ONEP) & mhi[i];
        uint32_t xlo = __vminu2(blo, rlo), xhi = __vminu2(bhi, rhi);
        xlo = __vminu2(__vminu2(xlo, (uint32_t)Df[i]), CLP);
        xhi = __vminu2(__vminu2(xhi, (uint32_t)(Df[i] >> 32)), CLP);
        sg[h0 + i][wid] = ((unsigned long long)xhi << 32) | xlo;
    }
    __syncthreads();

    unsigned long long* gp = g_pack + (size_t)b * SLICE;
    #pragma unroll
    for (int e = tid; e < Hx * 8; e += 256) {
        int h = e >> 3, wl = e & 7;
        gp[(size_t)h * Wx + w0 + wl] = sg[h][wl];
    }
}

// ---------------------------------------------------------------------------
// Rare exact tail for m > 16: full pruned scan from global packed g.
__device__ __noinline__ int tail_m(const unsigned long long* gr, int y, int sh) {
    int v0 = (int)((gr[y] >> sh) & 0xFFFF);
    int m = v0 * v0;
    for (int r = 1; r < Wx && r * r < m; ++r) {
        int jl = y - r, jr = y + r;
        if (jl >= 0) { int v = (int)((gr[jl] >> sh) & 0xFFFF); m = min(m, v * v + r * r); }
        if (jr < Wx) { int v = (int)((gr[jr] >> sh) & 0xFFFF); m = min(m, v * v + r * r); }
    }
    return m;
}

// ---------------------------------------------------------------------------
// Phase 2+3 fused + finalization: one block per (b,h) row, all 4 classes,
// fully branch-free per pixel.
//   dt_c(y) = sqrt( min_j g_c(j)^2 + (y-j)^2 )
// Fast path: m_f = min over |r|<=3 of min(g,255)^2 + r^2, computed for all 4
// classes with u16x2 SIMD. Exact when m_f <= 16 (any r>=4 or clamped
// candidate exceeds 16); otherwise rare exact tail. dt at the target class
// is 0 (g=0), so acc += sum_c p_c*dt_c needs no branch; S uses a select.
__global__ void __launch_bounds__(128) k_row(const float* __restrict__ outputs,
                                             const int*   __restrict__ targets,
                                             float*       __restrict__ out) {
    __shared__ uint32_t s_p01[Wx + 8];   // packed sq(c0)|sq(c1)<<16, +-4 pad
    __shared__ uint32_t s_p23[Wx + 8];
    __shared__ float s_red[4][9];
    __shared__ int s_last;

    int bh = blockIdx.x;               // 0 .. B*H-1
    int b  = bh / Hx;
    int h  = bh - b * Hx;

    const unsigned long long* gr = g_pack + (size_t)b * SLICE + (size_t)h * Wx;

    // build clamped-square packed arrays
    for (int i = threadIdx.x; i < Wx; i += 128) {
        unsigned long long v = gr[i];
        int v0 = min((int)(v & 0xFFFF), 255);
        int v1 = min((int)((v >> 16) & 0xFFFF), 255);
        int v2 = min((int)((v >> 32) & 0xFFFF), 255);
        int v3 = min((int)((v >> 48) & 0xFFFF), 255);
        s_p01[4 + i] = (uint32_t)(v0 * v0) | ((uint32_t)(v1 * v1) << 16);
        s_p23[4 + i] = (uint32_t)(v2 * v2) | ((uint32_t)(v3 * v3) << 16);
    }
    if (threadIdx.x < 8) {
        int o = threadIdx.x & 3;
        if (threadIdx.x < 4) { s_p01[o] = PADSQ; s_p23[o] = PADSQ; }
        else                 { s_p01[Wx + 4 + o] = PADSQ; s_p23[Wx + 4 + o] = PADSQ; }
    }
    __syncthreads();

    const float* ob = outputs + (size_t)b * Cx * SLICE + (size_t)h * Wx;
    const int*   tb = targets + (size_t)b * SLICE + (size_t)h * Wx;

    float acc = 0.0f;
    float Sv[Cx] = {0.0f, 0.0f, 0.0f, 0.0f};
    float Lm[Cx] = {0.0f, 0.0f, 0.0f, 0.0f};

    #pragma unroll
    for (int k = 0; k < Wx / 128; ++k) {
        int y = threadIdx.x + k * 128;

        float e0 = __expf(ob[y]);
        float e1 = __expf(ob[y + SLICE]);
        float e2 = __expf(ob[y + 2 * SLICE]);
        float e3 = __expf(ob[y + 3 * SLICE]);
        int   t  = tb[y];
        float inv = __fdividef(1.0f, e0 + e1 + e2 + e3);
        float p0 = e0 * inv, p1 = e1 * inv, p2 = e2 * inv, p3 = e3 * inv;

        // packed 4-class scan, radii 0..3 (branch-free)
        const uint32_t* P01 = &s_p01[4 + y];
        const uint32_t* P23 = &s_p23[4 + y];
        uint32_t m01 = P01[0];
        uint32_t m23 = P23[0];
        const uint32_t K1 = 0x00010001u, K2 = 0x00040004u, K3 = 0x00090009u;
        m01 = __vminu2(m01, __vaddus2(P01[-1], K1));
        m01 = __vminu2(m01, __vaddus2(P01[ 1], K1));
        m23 = __vminu2(m23, __vaddus2(P23[-1], K1));
        m23 = __vminu2(m23, __vaddus2(P23[ 1], K1));
        m01 = __vminu2(m01, __vaddus2(P01[-2], K2));
        m01 = __vminu2(m01, __vaddus2(P01[ 2], K2));
        m23 = __vminu2(m23, __vaddus2(P23[-2], K2));
        m23 = __vminu2(m23, __vaddus2(P23[ 2], K2));
        m01 = __vminu2(m01, __vaddus2(P01[-3], K3));
        m01 = __vminu2(m01, __vaddus2(P01[ 3], K3));
        m23 = __vminu2(m23, __vaddus2(P23[-3], K3));
        m23 = __vminu2(m23, __vaddus2(P23[ 3], K3));

        int m0 = (int)(m01 & 0xFFFFu), m1 = (int)(m01 >> 16);
        int m2 = (int)(m23 & 0xFFFFu), m3 = (int)(m23 >> 16);
        if (max(max(m0, m1), max(m2, m3)) > 16) {     // rare exact tail
            if (m0 > 16) m0 = tail_m(gr, y, 0);
            if (m1 > 16) m1 = tail_m(gr, y, 16);
            if (m2 > 16) m2 = tail_m(gr, y, 32);
            if (m3 > 16) m3 = tail_m(gr, y, 48);
        }
        float d0 = sqrt_approx((float)m0);
        float d1 = sqrt_approx((float)m1);
        float d2 = sqrt_approx((float)m2);
        float d3 = sqrt_approx((float)m3);

        acc += p0 * d0 + p1 * d1 + p2 * d2 + p3 * d3;   // dt at target class is 0
        Sv[0] += (t == 0) ? p0 : 0.0f;
        Sv[1] += (t == 1) ? p1 : 0.0f;
        Sv[2] += (t == 2) ? p2 : 0.0f;
        Sv[3] += (t == 3) ? p3 : 0.0f;
        Lm[0] = fmaxf(Lm[0], d0);
        Lm[1] = fmaxf(Lm[1], d1);
        Lm[2] = fmaxf(Lm[2], d2);
        Lm[3] = fmaxf(Lm[3], d3);
    }

    // block reduction
    #pragma unroll
    for (int off = 16; off > 0; off >>= 1) {
        acc += __shfl_down_sync(0xffffffffu, acc, off);
        #pragma unroll
        for (int c = 0; c < Cx; ++c) {
            Sv[c] += __shfl_down_sync(0xffffffffu, Sv[c], off);
            Lm[c]  = fmaxf(Lm[c], __shfl_down_sync(0xffffffffu, Lm[c], off));
        }
    }
    int wid = threadIdx.x >> 5;
    if ((threadIdx.x & 31) == 0) {
        s_red[wid][0] = acc;
        #pragma unroll
        for (int c = 0; c < Cx; ++c) { s_red[wid][1 + c] = Sv[c]; s_red[wid][5 + c] = Lm[c]; }
    }
    __syncthreads();
    if (threadIdx.x < Cx) {                 // threads 0..3: one class each
        int c = threadIdx.x;
        float s = s_red[0][1 + c] + s_red[1][1 + c] + s_red[2][1 + c] + s_red[3][1 + c];
        float m = fmaxf(fmaxf(s_red[0][5 + c], s_red[1][5 + c]),
                        fmaxf(s_red[2][5 + c], s_red[3][5 + c]));
        atomicAdd(&g_S[b * Cx + c], (double)s);
        atomicMax(&g_dmax_bits[b * Cx + c], __float_as_uint(m));
        if (c == 0) {
            double a = (double)s_red[0][0] + s_red[1][0] + s_red[2][0] + s_red[3][0];
            atomicAdd(&g_acc, a);
        }
        __threadfence();                    // release this block's contributions
    }
    __syncthreads();
    if (threadIdx.x == 0)
        s_last = (atomicAdd(&g_count, 1u) == (unsigned)(gridDim.x - 1));
    __syncthreads();

    if (s_last && threadIdx.x < 32) {
        __threadfence();                    // acquire all blocks' contributions
        double v = (double)__uint_as_float(((volatile unsigned int*)g_dmax_bits)[threadIdx.x])
                 * ((volatile double*)g_S)[threadIdx.x];
        #pragma unroll
        for (int off = 16; off > 0; off >>= 1)
            v += __shfl_down_sync(0xffffffffu, v, off);
        if (threadIdx.x == 0) {
            double a = *((volatile double*)&g_acc);
            out[0] = (float)((a - v) / ((double)Cx * (double)Bx * Cx * Hx * Wx));
            g_count = 0u;                   // reset for next (graph) replay
        }
    }
}

// ---------------------------------------------------------------------------
extern "C" void kernel_launch(void* const* d_in, const int* in_sizes, int n_in,
                              void* d_out, int out_size) {
    const float* outputs = (const float*)d_in[0];
    const int*   targets = (const int*)d_in[1];
    float*       out     = (float*)d_out;

    k_phase1<<<Bx * (Wx / 8), 256>>>(targets);
    k_row<<<Bx * Hx, 128>>>(outputs, targets, out);
}

// round 11
// speedup vs baseline: 1.0077x; 1.0077x over previous
#include <cuda_runtime.h>
#include <stdint.h>
#include <math.h>

#define Bx 8
#define Cx 4
#define Hx 384
#define Wx 384
#define SLICE (Hx*Wx)          // 147456
#define NSLICE (Bx*Cx)         // 32
#define BIGI 768               // = H + W, finite sentinel (matches reference)
#define INFP 0x3FFF3FFFu       // packed u16x2 "infinity" (saturating math keeps it big)
#define ONEP 0x00010001u
#define PADSQ 0xFE01FE01u      // packed 255^2: pad candidates always lose (>16)
#define ROWS 4                 // rows per k_row block

// Scratch (no cudaMalloc allowed).
__device__ unsigned long long g_pack[Bx*SLICE]; // [b][h][w] -> g for 4 classes, u16x4 (9 MB)
__device__ unsigned int   g_dmax_bits[NSLICE];
__device__ double         g_S[NSLICE];          // sum of p_c over target pixels
__device__ double         g_acc;                // sum of p_c * dt over non-target pixels
__device__ unsigned int   g_count;              // zero-init; reset by last k_row block

__device__ __forceinline__ float sqrt_approx(float x) {
    float r;
    asm("sqrt.approx.f32 %0, %1;" : "=f"(r) : "f"(x));
    return r;
}

// ---------------------------------------------------------------------------
// Phase 1: vertical 1D distance per (b,w) column for ALL 4 classes packed
// u16x4. One warp per column; lane owns a 12-pixel h-segment. Exact segmented
// min-plus scan; unclamped math + final clamp(768) == reference's per-step
// clamp since increments are +1.
__global__ void __launch_bounds__(256) k_phase1(const int* __restrict__ targets) {
    __shared__ unsigned long long sg[Hx][9];   // 27 KB staging (pad vs bank conflicts)

    int tid = threadIdx.x, wid = tid >> 5, lane = tid & 31;
    if (blockIdx.x == 0 && tid < NSLICE) {     // fused init
        g_dmax_bits[tid] = 0u; g_S[tid] = 0.0;
        if (tid == 0) g_acc = 0.0;
    }

    int b  = blockIdx.x / (Wx / 8);
    int w0 = (blockIdx.x % (Wx / 8)) * 8;
    int w  = w0 + wid;
    const int* tb = targets + (size_t)b * SLICE + w;
    int h0 = lane * 12;

    uint32_t mlo[12], mhi[12];
    #pragma unroll
    for (int i = 0; i < 12; ++i) {
        int t = __ldg(&tb[(h0 + i) * Wx]);
        mlo[i] = (t == 0) ? 0xFFFF0000u : (t == 1) ? 0x0000FFFFu : 0xFFFFFFFFu;
        mhi[i] = (t == 2) ? 0xFFFF0000u : (t == 3) ? 0x0000FFFFu : 0xFFFFFFFFu;
    }

    uint32_t flo = INFP, fhi = INFP;
    #pragma unroll
    for (int i = 0; i < 12; ++i) { flo = __vaddus2(flo, ONEP) & mlo[i]; fhi = __vaddus2(fhi, ONEP) & mhi[i]; }
    uint32_t blo = INFP, bhi = INFP;
    #pragma unroll
    for (int i = 11; i >= 0; --i) { blo = __vaddus2(blo, ONEP) & mlo[i]; bhi = __vaddus2(bhi, ONEP) & mhi[i]; }

    uint32_t filo = flo, fihi = fhi, bilo = blo, bihi = bhi;
    #pragma unroll
    for (int d = 1; d < 32; d <<= 1) {
        uint32_t k = ((12u * d) << 16) | (12u * d);
        uint32_t a0 = __shfl_up_sync(0xffffffffu, filo, d);
        uint32_t a1 = __shfl_up_sync(0xffffffffu, fihi, d);
        if (lane >= d) { filo = __vminu2(filo, __vaddus2(a0, k)); fihi = __vminu2(fihi, __vaddus2(a1, k)); }
        uint32_t c0 = __shfl_down_sync(0xffffffffu, bilo, d);
        uint32_t c1 = __shfl_down_sync(0xffffffffu, bihi, d);
        if (lane < 32 - d) { bilo = __vminu2(bilo, __vaddus2(c0, k)); bihi = __vminu2(bihi, __vaddus2(c1, k)); }
    }
    uint32_t cflo = __shfl_up_sync(0xffffffffu, filo, 1);
    uint32_t cfhi = __shfl_up_sync(0xffffffffu, fihi, 1);
    if (lane == 0) { cflo = INFP; cfhi = INFP; }
    uint32_t cblo = __shfl_down_sync(0xffffffffu, bilo, 1);
    uint32_t cbhi = __shfl_down_sync(0xffffffffu, bihi, 1);
    if (lane == 31) { cblo = INFP; cbhi = INFP; }

    unsigned long long Df[12];
    uint32_t rlo = cflo, rhi = cfhi;
    flo = INFP; fhi = INFP;
    #pragma unroll
    for (int i = 0; i < 12; ++i) {
        rlo = __vaddus2(rlo, ONEP); rhi = __vaddus2(rhi, ONEP);
        flo = __vaddus2(flo, ONEP) & mlo[i]; fhi = __vaddus2(fhi, ONEP) & mhi[i];
        uint32_t xlo = __vminu2(flo, rlo), xhi = __vminu2(fhi, rhi);
        Df[i] = ((unsigned long long)xhi << 32) | xlo;
    }
    const uint32_t CLP = ((uint32_t)BIGI << 16) | (uint32_t)BIGI;
    rlo = cblo; rhi = cbhi; blo = INFP; bhi = INFP;
    #pragma unroll
    for (int i = 11; i >= 0; --i) {
        rlo = __vaddus2(rlo, ONEP); rhi = __vaddus2(rhi, ONEP);
        blo = __vaddus2(blo, ONEP) & mlo[i]; bhi = __vaddus2(bhi, ONEP) & mhi[i];
        uint32_t xlo = __vminu2(blo, rlo), xhi = __vminu2(bhi, rhi);
        xlo = __vminu2(__vminu2(xlo, (uint32_t)Df[i]), CLP);
        xhi = __vminu2(__vminu2(xhi, (uint32_t)(Df[i] >> 32)), CLP);
        sg[h0 + i][wid] = ((unsigned long long)xhi << 32) | xlo;
    }
    __syncthreads();

    unsigned long long* gp = g_pack + (size_t)b * SLICE;
    #pragma unroll
    for (int e = tid; e < Hx * 8; e += 256) {
        int h = e >> 3, wl = e & 7;
        gp[(size_t)h * Wx + w0 + wl] = sg[h][wl];
    }
}

// ---------------------------------------------------------------------------
// Rare exact tail for m > 16: full pruned scan from global packed g.
__device__ __noinline__ int tail_m(const unsigned long long* gr, int y, int sh) {
    int v0 = (int)((gr[y] >> sh) & 0xFFFF);
    int m = v0 * v0;
    for (int r = 1; r < Wx && r * r < m; ++r) {
        int jl = y - r, jr = y + r;
        if (jl >= 0) { int v = (int)((gr[jl] >> sh) & 0xFFFF); m = min(m, v * v + r * r); }
        if (jr < Wx) { int v = (int)((gr[jr] >> sh) & 0xFFFF); m = min(m, v * v + r * r); }
    }
    return m;
}

// ---------------------------------------------------------------------------
// Phase 2+3 fused + finalization: one block per (b, 4-row band), all 4
// classes, branch-free per pixel.
//   dt_c(y) = sqrt( min_j g_c(j)^2 + (y-j)^2 )
// Fast path: m_f = min over |r|<=3 of min(g,255)^2 + r^2, all 4 classes via
// u16x2 SIMD on a uint2-interleaved shared row. Exact when m_f <= 16 (any
// r>=4 or clamped candidate exceeds 16); else rare exact tail. dt at the
// target class is 0 (g=0), so acc needs no branch; S uses a select.
__global__ void __launch_bounds__(128) k_row(const float* __restrict__ outputs,
                                             const int*   __restrict__ targets,
                                             float*       __restrict__ out) {
    __shared__ uint2 s_p[ROWS][Wx + 8];   // {p01,p23} per pixel, +-4 pad; 12.5 KB
    __shared__ float s_red[4][9];
    __shared__ int s_last;

    int band = blockIdx.x;             // 0 .. B*H/ROWS-1
    int b    = band / (Hx / ROWS);
    int h0   = (band % (Hx / ROWS)) * ROWS;

    const unsigned long long* gband = g_pack + (size_t)b * SLICE + (size_t)h0 * Wx;

    // build clamped-square packed arrays for the 4 rows
    for (int i = threadIdx.x; i < ROWS * Wx; i += 128) {
        int r = i / Wx, x = i - r * Wx;
        unsigned long long v = gband[i];
        int v0 = min((int)(v & 0xFFFF), 255);
        int v1 = min((int)((v >> 16) & 0xFFFF), 255);
        int v2 = min((int)((v >> 32) & 0xFFFF), 255);
        int v3 = min((int)((v >> 48) & 0xFFFF), 255);
        s_p[r][4 + x] = make_uint2((uint32_t)(v0 * v0) | ((uint32_t)(v1 * v1) << 16),
                                   (uint32_t)(v2 * v2) | ((uint32_t)(v3 * v3) << 16));
    }
    if (threadIdx.x < ROWS * 8) {
        int r = threadIdx.x >> 3, o = threadIdx.x & 7;
        int idx = (o < 4) ? o : (Wx + o);
        s_p[r][idx] = make_uint2(PADSQ, PADSQ);
    }
    __syncthreads();

    float acc = 0.0f;
    float Sv[Cx] = {0.0f, 0.0f, 0.0f, 0.0f};
    int   Mm[Cx] = {0, 0, 0, 0};            // per-class max of m (sqrt monotone)

    #pragma unroll
    for (int rw = 0; rw < ROWS; ++rw) {
        const float* ob = outputs + (size_t)b * Cx * SLICE + (size_t)(h0 + rw) * Wx;
        const int*   tb = targets + (size_t)b * SLICE + (size_t)(h0 + rw) * Wx;
        const unsigned long long* gr = gband + (size_t)rw * Wx;

        #pragma unroll
        for (int k = 0; k < Wx / 128; ++k) {
            int y = threadIdx.x + k * 128;

            float e0 = __expf(ob[y]);
            float e1 = __expf(ob[y + SLICE]);
            float e2 = __expf(ob[y + 2 * SLICE]);
            float e3 = __expf(ob[y + 3 * SLICE]);
            int   t  = tb[y];
            float inv = __fdividef(1.0f, e0 + e1 + e2 + e3);
            float p0 = e0 * inv, p1 = e1 * inv, p2 = e2 * inv, p3 = e3 * inv;

            // packed 4-class scan, radii 0..3 (branch-free), uint2 LDS
            const uint2* P = &s_p[rw][4 + y];
            uint2 q0 = P[0];
            uint32_t m01 = q0.x, m23 = q0.y;
            const uint32_t K1 = 0x00010001u, K2 = 0x00040004u, K3 = 0x00090009u;
            uint2 qa = P[-1], qb = P[1];
            m01 = __vminu2(m01, __vaddus2(qa.x, K1));
            m23 = __vminu2(m23, __vaddus2(qa.y, K1));
            m01 = __vminu2(m01, __vaddus2(qb.x, K1));
            m23 = __vminu2(m23, __vaddus2(qb.y, K1));
            qa = P[-2]; qb = P[2];
            m01 = __vminu2(m01, __vaddus2(qa.x, K2));
            m23 = __vminu2(m23, __vaddus2(qa.y, K2));
            m01 = __vminu2(m01, __vaddus2(qb.x, K2));
            m23 = __vminu2(m23, __vaddus2(qb.y, K2));
            qa = P[-3]; qb = P[3];
            m01 = __vminu2(m01, __vaddus2(qa.x, K3));
            m23 = __vminu2(m23, __vaddus2(qa.y, K3));
            m01 = __vminu2(m01, __vaddus2(qb.x, K3));
            m23 = __vminu2(m23, __vaddus2(qb.y, K3));

            int m0 = (int)(m01 & 0xFFFFu), m1 = (int)(m01 >> 16);
            int m2 = (int)(m23 & 0xFFFFu), m3 = (int)(m23 >> 16);
            if (max(max(m0, m1), max(m2, m3)) > 16) {     // rare exact tail
                if (m0 > 16) m0 = tail_m(gr, y, 0);
                if (m1 > 16) m1 = tail_m(gr, y, 16);
                if (m2 > 16) m2 = tail_m(gr, y, 32);
                if (m3 > 16) m3 = tail_m(gr, y, 48);
            }
            float d0 = sqrt_approx((float)m0);
            float d1 = sqrt_approx((float)m1);
            float d2 = sqrt_approx((float)m2);
            float d3 = sqrt_approx((float)m3);

            acc += p0 * d0 + p1 * d1 + p2 * d2 + p3 * d3;  // dt at target class = 0
            Sv[0] += (t == 0) ? p0 : 0.0f;
            Sv[1] += (t == 1) ? p1 : 0.0f;
            Sv[2] += (t == 2) ? p2 : 0.0f;
            Sv[3] += (t == 3) ? p3 : 0.0f;
            Mm[0] = max(Mm[0], m0);
            Mm[1] = max(Mm[1], m1);
            Mm[2] = max(Mm[2], m2);
            Mm[3] = max(Mm[3], m3);
        }
    }

    // block reduction (sqrt is monotone -> reduce m as int, sqrt once)
    float Lm[Cx];
    #pragma unroll
    for (int c = 0; c < Cx; ++c) Lm[c] = sqrt_approx((float)Mm[c]);
    #pragma unroll
    for (int off = 16; off > 0; off >>= 1) {
        acc += __shfl_down_sync(0xffffffffu, acc, off);
        #pragma unroll
        for (int c = 0; c < Cx; ++c) {
            Sv[c] += __shfl_down_sync(0xffffffffu, Sv[c], off);
            Lm[c]  = fmaxf(Lm[c], __shfl_down_sync(0xffffffffu, Lm[c], off));
        }
    }
    int wid = threadIdx.x >> 5;
    if ((threadIdx.x & 31) == 0) {
        s_red[wid][0] = acc;
        #pragma unroll
        for (int c = 0; c < Cx; ++c) { s_red[wid][1 + c] = Sv[c]; s_red[wid][5 + c] = Lm[c]; }
    }
    __syncthreads();
    if (threadIdx.x < Cx) {                 // threads 0..3: one class each
        int c = threadIdx.x;
        float s = s_red[0][1 + c] + s_red[1][1 + c] + s_red[2][1 + c] + s_red[3][1 + c];
        float m = fmaxf(fmaxf(s_red[0][5 + c], s_red[1][5 + c]),
                        fmaxf(s_red[2][5 + c], s_red[3][5 + c]));
        atomicAdd(&g_S[b * Cx + c], (double)s);
        atomicMax(&g_dmax_bits[b * Cx + c], __float_as_uint(m));
        if (c == 0) {
            double a = (double)s_red[0][0] + s_red[1][0] + s_red[2][0] + s_red[3][0];
            atomicAdd(&g_acc, a);
        }
        __threadfence();                    // release this block's contributions
    }
    __syncthreads();
    if (threadIdx.x == 0)
        s_last = (atomicAdd(&g_count, 1u) == (unsigned)(gridDim.x - 1));
    __syncthreads();

    if (s_last && threadIdx.x < 32) {
        __threadfence();                    // acquire all blocks' contributions
        double v = (double)__uint_as_float(((volatile unsigned int*)g_dmax_bits)[threadIdx.x])
                 * ((volatile double*)g_S)[threadIdx.x];
        #pragma unroll
        for (int off = 16; off > 0; off >>= 1)
            v += __shfl_down_sync(0xffffffffu, v, off);
        if (threadIdx.x == 0) {
            double a = *((volatile double*)&g_acc);
            out[0] = (float)((a - v) / ((double)Cx * (double)Bx * Cx * Hx * Wx));
            g_count = 0u;                   // reset for next (graph) replay
        }
    }
}

// ---------------------------------------------------------------------------
extern "C" void kernel_launch(void* const* d_in, const int* in_sizes, int n_in,
                              void* d_out, int out_size) {
    const float* outputs = (const float*)d_in[0];
    const int*   targets = (const int*)d_in[1];
    float*       out     = (float*)d_out;

    k_phase1<<<Bx * (Wx / 8), 256>>>(targets);
    k_row<<<Bx * Hx / ROWS, 128>>>(outputs, targets, out);
}